// round 1
// baseline (speedup 1.0000x reference)
#include <cuda_runtime.h>
#include <cstdint>

// ---------------------------------------------------------------------------
// SparseGaussianHead: two sparse-conv layers (27-offset gather-GEMM) + GELU
//   L1: [400k x 64] -> [400k x 38]   (padded N to 40)
//   L2: [400k x 38] -> [400k x 38]   (padded K and N to 40)
// TF32 mma.sync.m16n8k8, fp32 accumulate. All operands rounded with
// cvt.rna.tf32.f32 to keep rounding error zero-mean (~2.8e-4 RMS / operand).
// ---------------------------------------------------------------------------

#define NPTS 400000
#define NOFF 27

// Scratch (device globals: allocation-free rule)
__device__ float g_featp[NPTS * 64];      // features pre-rounded to tf32
__device__ float g_h[NPTS * 40];          // intermediate (gelu output), cols 38..39 = 0
__device__ float g_W1p[NOFF * 64 * 40];   // W1 padded + tf32-rounded
__device__ float g_W2p[NOFF * 40 * 40];   // W2 padded + tf32-rounded

__device__ __forceinline__ float tf32r(float x) {
    unsigned u;
    asm("cvt.rna.tf32.f32 %0, %1;" : "=r"(u) : "f"(x));
    return __uint_as_float(u);
}

__device__ __forceinline__ float gelu_exact(float x) {
    return 0.5f * x * (1.0f + erff(x * 0.7071067811865476f));
}

// ------------------------------ prep kernels ------------------------------

__global__ void prep_feat(const float* __restrict__ F) {
    int e = blockIdx.x * 256 + threadIdx.x;   // grid covers NPTS*64 exactly
    g_featp[e] = tf32r(F[e]);
}

__global__ void prep_w1(const float* __restrict__ W1) {
    int e = blockIdx.x * 256 + threadIdx.x;
    if (e >= NOFF * 64 * 40) return;
    int c = e % 40;
    int rest = e / 40;
    int ci = rest % 64;
    int k = rest / 64;
    float v = (c < 38) ? W1[(k * 64 + ci) * 38 + c] : 0.0f;
    g_W1p[e] = tf32r(v);
}

__global__ void prep_w2(const float* __restrict__ W2) {
    int e = blockIdx.x * 256 + threadIdx.x;
    if (e >= NOFF * 40 * 40) return;
    int c = e % 40;
    int rest = e / 40;
    int ci = rest % 40;
    int k = rest / 40;
    float v = (c < 38 && ci < 38) ? W2[(k * 38 + ci) * 38 + c] : 0.0f;
    g_W2p[e] = tf32r(v);
}

// ------------------------------ conv kernel -------------------------------
// MODE 0: in = g_featp (KD=64), out = g_h with exact-GELU + tf32 rounding
// MODE 1: in = g_h    (KD=40), out = d_out (first 38 cols)

template <int KD, int MODE>
__global__ __launch_bounds__(256) void conv_k(const int* __restrict__ nbr,
                                              float* __restrict__ dout) {
    constexpr int KD4 = KD / 4;
    constexpr int AS  = KD + 4;          // padded smem stride (bank-conflict-free)
    __shared__ float As[128 * AS];
    __shared__ float Ws[KD * 40];

    const float* __restrict__ feat = (MODE == 0) ? g_featp : g_h;
    const float* __restrict__ Wg   = (MODE == 0) ? g_W1p   : g_W2p;

    const int tid  = threadIdx.x;
    const int warp = tid >> 5;
    const int lane = tid & 31;
    const int g    = lane >> 2;   // group id (0..7)
    const int t    = lane & 3;    // thread in group (0..3)
    const int base = blockIdx.x * 128;

    float acc[5][4];
#pragma unroll
    for (int j = 0; j < 5; j++)
#pragma unroll
        for (int q = 0; q < 4; q++) acc[j][q] = 0.0f;

    const float4* __restrict__ feat4 = (const float4*)feat;

    for (int k = 0; k < NOFF; k++) {
        __syncthreads();   // previous iteration's MMAs done reading smem

        // --- gather A tile: 128 rows x KD floats ---
        const int* __restrict__ nbrk = nbr + k * NPTS + base;
#pragma unroll
        for (int it = 0; it < (128 * KD4) / 256; ++it) {
            int e = tid + it * 256;
            int r = e / KD4;
            int c = e - r * KD4;
            int idx = nbrk[r];
            float4 v = make_float4(0.f, 0.f, 0.f, 0.f);
            if ((unsigned)idx < (unsigned)NPTS)
                v = __ldg(&feat4[idx * KD4 + c]);
            *(float4*)&As[r * AS + 4 * c] = v;
        }
        // --- load W[k]: KD x 40 ---
        const float4* __restrict__ Wk4 = (const float4*)(Wg + k * KD * 40);
        for (int e = tid; e < KD * 10; e += 256)
            ((float4*)Ws)[e] = __ldg(&Wk4[e]);

        __syncthreads();

        // --- MMA: [128 x KD] @ [KD x 40], warp w owns rows 16w..16w+15 ---
        const int arow = warp * 16 + g;
#pragma unroll
        for (int kk = 0; kk < KD / 8; ++kk) {
            const int kc = kk * 8 + t;
            unsigned a0 = __float_as_uint(As[arow * AS + kc]);
            unsigned a1 = __float_as_uint(As[(arow + 8) * AS + kc]);
            unsigned a2 = __float_as_uint(As[arow * AS + kc + 4]);
            unsigned a3 = __float_as_uint(As[(arow + 8) * AS + kc + 4]);
#pragma unroll
            for (int j = 0; j < 5; j++) {
                unsigned b0 = __float_as_uint(Ws[kc * 40 + j * 8 + g]);
                unsigned b1 = __float_as_uint(Ws[(kc + 4) * 40 + j * 8 + g]);
                asm volatile(
                    "mma.sync.aligned.m16n8k8.row.col.f32.tf32.tf32.f32 "
                    "{%0,%1,%2,%3}, {%4,%5,%6,%7}, {%8,%9}, {%0,%1,%2,%3};\n"
                    : "+f"(acc[j][0]), "+f"(acc[j][1]),
                      "+f"(acc[j][2]), "+f"(acc[j][3])
                    : "r"(a0), "r"(a1), "r"(a2), "r"(a3), "r"(b0), "r"(b1));
            }
        }
    }

    // --- epilogue ---
    const int r0 = base + warp * 16 + g;
#pragma unroll
    for (int j = 0; j < 5; j++) {
        const int c0 = j * 8 + 2 * t;
        if (MODE == 0) {
            g_h[r0 * 40 + c0]           = tf32r(gelu_exact(acc[j][0]));
            g_h[r0 * 40 + c0 + 1]       = tf32r(gelu_exact(acc[j][1]));
            g_h[(r0 + 8) * 40 + c0]     = tf32r(gelu_exact(acc[j][2]));
            g_h[(r0 + 8) * 40 + c0 + 1] = tf32r(gelu_exact(acc[j][3]));
        } else {
            if (c0 < 38) {
                dout[r0 * 38 + c0]       = acc[j][0];
                dout[(r0 + 8) * 38 + c0] = acc[j][2];
            }
            if (c0 + 1 < 38) {
                dout[r0 * 38 + c0 + 1]       = acc[j][1];
                dout[(r0 + 8) * 38 + c0 + 1] = acc[j][3];
            }
        }
    }
}

// ------------------------------ launch ------------------------------------

extern "C" void kernel_launch(void* const* d_in, const int* in_sizes, int n_in,
                              void* d_out, int out_size) {
    const float* F   = (const float*)d_in[0];   // [400000, 64]
    const int*   nbr = (const int*)d_in[1];     // [27, 400000]
    const float* W1  = (const float*)d_in[2];   // [27, 64, 38]
    const float* W2  = (const float*)d_in[3];   // [27, 38, 38]
    float* out = (float*)d_out;                 // [400000, 38]

    prep_feat<<<(NPTS * 64) / 256, 256>>>(F);               // exact multiple
    prep_w1<<<(NOFF * 64 * 40 + 255) / 256, 256>>>(W1);
    prep_w2<<<(NOFF * 40 * 40 + 255) / 256, 256>>>(W2);

    conv_k<64, 0><<<NPTS / 128, 256>>>(nbr, nullptr);       // L1 + GELU -> g_h
    conv_k<40, 1><<<NPTS / 128, 256>>>(nbr, out);           // L2 -> d_out
}

// round 2
// speedup vs baseline: 1.6508x; 1.6508x over previous
#include <cuda_runtime.h>
#include <cstdint>

// ---------------------------------------------------------------------------
// SparseGaussianHead: two sparse-conv layers (27-offset gather-GEMM) + GELU
//   L1: [400k x 64] -> [400k x 38]   (padded N to 40)
//   L2: [400k x 38] -> [400k x 38]   (padded K and N to 40)
// TF32 mma.sync.m16n8k8, fp32 accumulate, cvt.rna.tf32 pre-rounding.
// R2: 4 warps x 32 rows (B-fragment reuse across 2 row tiles) + cp.async.cg
//     gather (single L1 traversal, zero-fill for padding index).
// ---------------------------------------------------------------------------

#define NPTS 400000
#define NOFF 27

__device__ float g_featp[NPTS * 64];      // features pre-rounded to tf32
__device__ float g_h[NPTS * 40];          // intermediate (gelu out), cols 38..39 = 0
__device__ float g_W1p[NOFF * 64 * 40];   // W1 padded + tf32-rounded
__device__ float g_W2p[NOFF * 40 * 40];   // W2 padded + tf32-rounded

__device__ __forceinline__ float tf32r(float x) {
    unsigned u;
    asm("cvt.rna.tf32.f32 %0, %1;" : "=r"(u) : "f"(x));
    return __uint_as_float(u);
}

__device__ __forceinline__ float gelu_exact(float x) {
    return 0.5f * x * (1.0f + erff(x * 0.7071067811865476f));
}

// ------------------------------ prep kernels ------------------------------

__global__ void prep_feat(const float* __restrict__ F) {
    int e = blockIdx.x * 256 + threadIdx.x;   // grid covers NPTS*64 exactly
    g_featp[e] = tf32r(F[e]);
}

__global__ void prep_w1(const float* __restrict__ W1) {
    int e = blockIdx.x * 256 + threadIdx.x;
    if (e >= NOFF * 64 * 40) return;
    int c = e % 40;
    int rest = e / 40;
    int ci = rest % 64;
    int k = rest / 64;
    float v = (c < 38) ? W1[(k * 64 + ci) * 38 + c] : 0.0f;
    g_W1p[e] = tf32r(v);
}

__global__ void prep_w2(const float* __restrict__ W2) {
    int e = blockIdx.x * 256 + threadIdx.x;
    if (e >= NOFF * 40 * 40) return;
    int c = e % 40;
    int rest = e / 40;
    int ci = rest % 40;
    int k = rest / 40;
    float v = (c < 38 && ci < 38) ? W2[(k * 38 + ci) * 38 + c] : 0.0f;
    g_W2p[e] = tf32r(v);
}

// ------------------------------ conv kernel -------------------------------
// 128 threads = 4 warps. CTA tile: 128 rows x 40 cols.
// Each warp owns 32 rows = two m16 tiles -> B fragments reused 2x.
// MODE 0: in = g_featp (KD=64), out = g_h with exact-GELU + tf32 rounding
// MODE 1: in = g_h    (KD=40), out = d_out (first 38 cols)

template <int KD, int MODE>
__global__ __launch_bounds__(128) void conv_k(const int* __restrict__ nbr,
                                              float* __restrict__ dout) {
    constexpr int KD4 = KD / 4;
    constexpr int AS  = KD + 4;          // padded smem stride (bank-conflict-free)
    __shared__ float As[128 * AS];
    __shared__ float Ws[KD * 40];

    const float* __restrict__ feat = (MODE == 0) ? g_featp : g_h;
    const float* __restrict__ Wg   = (MODE == 0) ? g_W1p   : g_W2p;

    const int tid  = threadIdx.x;
    const int warp = tid >> 5;
    const int lane = tid & 31;
    const int g    = lane >> 2;   // group id (0..7)
    const int t    = lane & 3;    // thread in group (0..3)
    const int base = blockIdx.x * 128;

    const unsigned as_base = (unsigned)__cvta_generic_to_shared(As);
    const unsigned ws_base = (unsigned)__cvta_generic_to_shared(Ws);

    float acc[2][5][4];
#pragma unroll
    for (int tt = 0; tt < 2; tt++)
#pragma unroll
        for (int j = 0; j < 5; j++)
#pragma unroll
            for (int q = 0; q < 4; q++) acc[tt][j][q] = 0.0f;

    const float4* __restrict__ feat4 = (const float4*)feat;

    for (int k = 0; k < NOFF; k++) {
        __syncthreads();   // previous iteration's MMAs done reading smem

        // --- gather A tile via cp.async: thread tid owns row tid ---
        {
            const int idx = nbr[k * NPTS + base + tid];
            const unsigned vsz = ((unsigned)idx < (unsigned)NPTS) ? 16u : 0u;
            const float4* src = feat4 + (size_t)(vsz ? idx : 0) * KD4;
            const unsigned dst = as_base + (unsigned)(tid * AS) * 4u;
#pragma unroll
            for (int c = 0; c < KD4; c++) {
                asm volatile(
                    "cp.async.cg.shared.global [%0], [%1], 16, %2;\n"
                    :: "r"(dst + (unsigned)(16 * c)), "l"(src + c), "r"(vsz));
            }
        }
        // --- load W[k] (KD x 40) via cp.async ---
        {
            const float4* wsrc = (const float4*)(Wg + k * KD * 40);
#pragma unroll
            for (int e = tid; e < KD * 10; e += 128) {
                asm volatile(
                    "cp.async.cg.shared.global [%0], [%1], 16, 16;\n"
                    :: "r"(ws_base + (unsigned)(16 * e)), "l"(wsrc + e));
            }
        }
        asm volatile("cp.async.commit_group;\n" ::: "memory");
        asm volatile("cp.async.wait_group 0;\n" ::: "memory");
        __syncthreads();

        // --- MMA: [128 x KD] @ [KD x 40], warp w owns rows 32w..32w+31 ---
#pragma unroll
        for (int kk = 0; kk < KD / 8; ++kk) {
            const int kc = kk * 8 + t;
            unsigned a[2][4];
#pragma unroll
            for (int tt = 0; tt < 2; tt++) {
                const int arow = warp * 32 + tt * 16 + g;
                a[tt][0] = __float_as_uint(As[arow * AS + kc]);
                a[tt][1] = __float_as_uint(As[(arow + 8) * AS + kc]);
                a[tt][2] = __float_as_uint(As[arow * AS + kc + 4]);
                a[tt][3] = __float_as_uint(As[(arow + 8) * AS + kc + 4]);
            }
#pragma unroll
            for (int j = 0; j < 5; j++) {
                const unsigned b0 = __float_as_uint(Ws[kc * 40 + j * 8 + g]);
                const unsigned b1 = __float_as_uint(Ws[(kc + 4) * 40 + j * 8 + g]);
#pragma unroll
                for (int tt = 0; tt < 2; tt++) {
                    asm volatile(
                        "mma.sync.aligned.m16n8k8.row.col.f32.tf32.tf32.f32 "
                        "{%0,%1,%2,%3}, {%4,%5,%6,%7}, {%8,%9}, {%0,%1,%2,%3};\n"
                        : "+f"(acc[tt][j][0]), "+f"(acc[tt][j][1]),
                          "+f"(acc[tt][j][2]), "+f"(acc[tt][j][3])
                        : "r"(a[tt][0]), "r"(a[tt][1]), "r"(a[tt][2]),
                          "r"(a[tt][3]), "r"(b0), "r"(b1));
                }
            }
        }
    }

    // --- epilogue ---
#pragma unroll
    for (int tt = 0; tt < 2; tt++) {
        const int r0 = base + warp * 32 + tt * 16 + g;
#pragma unroll
        for (int j = 0; j < 5; j++) {
            const int c0 = j * 8 + 2 * t;
            if (MODE == 0) {
                g_h[r0 * 40 + c0]           = tf32r(gelu_exact(acc[tt][j][0]));
                g_h[r0 * 40 + c0 + 1]       = tf32r(gelu_exact(acc[tt][j][1]));
                g_h[(r0 + 8) * 40 + c0]     = tf32r(gelu_exact(acc[tt][j][2]));
                g_h[(r0 + 8) * 40 + c0 + 1] = tf32r(gelu_exact(acc[tt][j][3]));
            } else {
                if (c0 < 38) {
                    dout[r0 * 38 + c0]       = acc[tt][j][0];
                    dout[(r0 + 8) * 38 + c0] = acc[tt][j][2];
                }
                if (c0 + 1 < 38) {
                    dout[r0 * 38 + c0 + 1]       = acc[tt][j][1];
                    dout[(r0 + 8) * 38 + c0 + 1] = acc[tt][j][3];
                }
            }
        }
    }
}

// ------------------------------ launch ------------------------------------

extern "C" void kernel_launch(void* const* d_in, const int* in_sizes, int n_in,
                              void* d_out, int out_size) {
    const float* F   = (const float*)d_in[0];   // [400000, 64]
    const int*   nbr = (const int*)d_in[1];     // [27, 400000]
    const float* W1  = (const float*)d_in[2];   // [27, 64, 38]
    const float* W2  = (const float*)d_in[3];   // [27, 38, 38]
    float* out = (float*)d_out;                 // [400000, 38]

    prep_feat<<<(NPTS * 64) / 256, 256>>>(F);               // exact multiple
    prep_w1<<<(NOFF * 64 * 40 + 255) / 256, 256>>>(W1);
    prep_w2<<<(NOFF * 40 * 40 + 255) / 256, 256>>>(W2);

    conv_k<64, 0><<<NPTS / 128, 128>>>(nbr, nullptr);       // L1 + GELU -> g_h
    conv_k<40, 1><<<NPTS / 128, 128>>>(nbr, out);           // L2 -> d_out
}